// round 12
// baseline (speedup 1.0000x reference)
#include <cuda_runtime.h>
#include <cuda_fp16.h>
#include <math.h>

#define NUM_WIRES 18
#define BATCH     64
#define NPAIR     32
#define GP        16               // pairs per L2-resident group (2 groups)
#define DIM       262144           // 2^18
#define CHUNK_BITS 13
#define CHUNK     8192
#define NCHUNK    32
#define PL_THREADS 512
#define PH_THREADS 256

typedef unsigned long long u64;

// SoA component planes; each half2 = (state_s0, state_s1)
__device__ __half2 g_re0[NPAIR * DIM];
__device__ __half2 g_im0[NPAIR * DIM];
__device__ __half2 g_re1[NPAIR * DIM];
__device__ __half2 g_im1[NPAIR * DIM];
__device__ float g_partial[BATCH * NCHUNK * NUM_WIRES];

// ---- packed f32x2 primitives ----
__device__ __forceinline__ u64 pk(float lo, float hi) {
    u64 r; asm("mov.b64 %0,{%1,%2};" : "=l"(r) : "f"(lo), "f"(hi)); return r;
}
__device__ __forceinline__ u64 pk2(float x) { return pk(x, x); }
__device__ __forceinline__ float2 up(u64 v) {
    float2 f; asm("mov.b64 {%0,%1},%2;" : "=f"(f.x), "=f"(f.y) : "l"(v)); return f;
}
__device__ __forceinline__ u64 fma2(u64 a, u64 b, u64 c) {
    u64 d; asm("fma.rn.f32x2 %0,%1,%2,%3;" : "=l"(d) : "l"(a), "l"(b), "l"(c)); return d;
}
__device__ __forceinline__ u64 mul2(u64 a, u64 b) {
    u64 d; asm("mul.rn.f32x2 %0,%1,%2;" : "=l"(d) : "l"(a), "l"(b)); return d;
}
__device__ __forceinline__ u64 h2u_pk(unsigned v) {
    __half2 h; *(unsigned*)&h = v; float2 f = __half22float2(h); return pk(f.x, f.y);
}
__device__ __forceinline__ unsigned pk2hu(u64 v) {
    float2 f = up(v); __half2 h = __floats2half2_rn(f.x, f.y); return *(unsigned*)&h;
}

// fold-XOR swizzle on 4B-word index: bank bit i = e_i ^ e_{i+5} ^ e_{i+10}
__device__ __forceinline__ int SWX(int e) { return e ^ ((e >> 5) & 31) ^ ((e >> 10) & 31); }
__device__ __forceinline__ int invgray(int t) {
    t ^= t >> 1; t ^= t >> 2; t ^= t >> 4; t ^= t >> 8; return t;
}

// real RY butterfly on packed pair (a = bit0 branch)
__device__ __forceinline__ void ry1(u64& a, u64& b, u64 c, u64 s, u64 ns) {
    u64 na = fma2(c, a, mul2(ns, b));
    b = fma2(s, a, mul2(c, b));
    a = na;
}
// complex phase multiply on packed amplitude
__device__ __forceinline__ void capply(u64& r, u64& i, float2 p) {
    u64 pr = pk2(p.x), pi = pk2(p.y), npi = pk2(-p.y);
    u64 nr = fma2(pr, r, mul2(npi, i));
    i = fma2(pr, i, mul2(pi, r));
    r = nr;
}
__device__ __forceinline__ float2 cmulf(float2 a, float2 b) {
    return make_float2(a.x * b.x - a.y * b.y, a.x * b.y + a.y * b.x);
}
__device__ __forceinline__ void st_pair(__half2* pl, int q, u64 A, u64 B) {
    unsigned va = pk2hu(A), vb = pk2hu(B);
    uint2 o; o.x = (q & 1) ? vb : va; o.y = (q & 1) ? va : vb;
    *(uint2*)(pl + (q & ~1)) = o;
}

// ---------------------------------------------------------------------------
// pass_high: RY-only, wires 0..4 (bits 17..13), per component plane, in place.
// ---------------------------------------------------------------------------
__global__ void __launch_bounds__(PH_THREADS, 2)
k_pass_high(__half2* __restrict__ bre, __half2* __restrict__ bim,
            const float* __restrict__ params, int layer) {
    int gid = blockIdx.x * PH_THREADS + threadIdx.x;
    int u = gid & (CHUNK - 1);
    int r = gid >> CHUNK_BITS;
    __half2* pl = ((r & 1) ? bim : bre) + (long)(r >> 1) * DIM + u;

    u64 x[32];
#pragma unroll
    for (int h = 0; h < 2; ++h) {
        unsigned hb[16];
#pragma unroll
        for (int j = 0; j < 16; ++j)
            hb[j] = *(const unsigned*)(pl + ((long)(h * 16 + j) << CHUNK_BITS));
#pragma unroll
        for (int j = 0; j < 16; ++j) x[h * 16 + j] = h2u_pk(hb[j]);
    }
#pragma unroll
    for (int w = 0; w < 5; ++w) {
        float ty = params[(layer * 2) * NUM_WIRES + w] * 0.5f;
        float sy, cy; sincosf(ty, &sy, &cy);
        u64 c = pk2(cy), s = pk2(sy), ns = pk2(-sy);
        int m = 16 >> w;
#pragma unroll
        for (int j = 0; j < 32; ++j)
            if (!(j & m)) ry1(x[j], x[j | m], c, s, ns);
    }
#pragma unroll
    for (int j = 0; j < 32; ++j)
        *(unsigned*)(pl + ((long)j << CHUNK_BITS)) = pk2hu(x[j]);
}

// layer-0 variant: fp32 inputs (rows 2p, 2p+1) -> packed half2 planes
__global__ void __launch_bounds__(PH_THREADS, 2)
k_first(const float* __restrict__ sre, const float* __restrict__ sim,
        __half2* __restrict__ ore, __half2* __restrict__ oim,
        const float* __restrict__ params) {
    int gid = blockIdx.x * PH_THREADS + threadIdx.x;
    int u = gid & (CHUNK - 1);
    int r = gid >> CHUNK_BITS;
    int c = r & 1, p = r >> 1;
    const float* src = c ? sim : sre;
    const float* r0 = src + (long)(2 * p) * DIM + u;
    const float* r1 = src + (long)(2 * p + 1) * DIM + u;

    u64 x[32];
#pragma unroll
    for (int j = 0; j < 32; ++j)
        x[j] = pk(r0[(long)j << CHUNK_BITS], r1[(long)j << CHUNK_BITS]);
#pragma unroll
    for (int w = 0; w < 5; ++w) {
        float ty = params[w] * 0.5f;
        float sy, cy; sincosf(ty, &sy, &cy);
        u64 cc = pk2(cy), s = pk2(sy), ns = pk2(-sy);
        int m = 16 >> w;
#pragma unroll
        for (int j = 0; j < 32; ++j)
            if (!(j & m)) ry1(x[j], x[j | m], cc, s, ns);
    }
    __half2* pl = (c ? oim : ore) + (long)p * DIM + u;
#pragma unroll
    for (int j = 0; j < 32; ++j)
        *(unsigned*)(pl + ((long)j << CHUNK_BITS)) = pk2hu(x[j]);
}

// 4-bit RY stage on ONE plane: 16 values per group, bit offset sh.
__device__ __forceinline__ void stage4p(unsigned* pl, const u64 (*sg)[3],
                                        int base, int sh, int wi0) {
    u64 x[16];
#pragma unroll
    for (int j = 0; j < 16; ++j) x[j] = h2u_pk(pl[SWX(base | (j << sh))]);
#pragma unroll
    for (int p = 0; p < 4; ++p) {
        u64 c = sg[wi0 - p][0], s = sg[wi0 - p][1], ns = sg[wi0 - p][2];
        int m = 1 << p;
#pragma unroll
        for (int j = 0; j < 16; ++j)
            if (!(j & m)) ry1(x[j], x[j | m], c, s, ns);
    }
#pragma unroll
    for (int j = 0; j < 16; ++j) pl[SWX(base | (j << sh))] = pk2hu(x[j]);
}

// ---------------------------------------------------------------------------
// pass_low: wires 5..17 (bits 12..0); fp16 smem (64KB -> 2 CTAs/SM).
// Fill fuses the bits 0..3 stage (wires 17..14) in registers; then two
// 4-bit smem stages (bits 4..7, 8..11); wire 5 (bit 12) + diagonal RZ phase
// fused with the Gray scatter. LAST: expectation values, no RZ.
// ---------------------------------------------------------------------------
template <int LAST>
__global__ void __launch_bounds__(PL_THREADS, 2)
k_pass_low(const __half2* __restrict__ ire, const __half2* __restrict__ iim,
           __half2* __restrict__ ore, __half2* __restrict__ oim,
           const float* __restrict__ params, float* __restrict__ partial,
           int layer) {
    extern __shared__ unsigned smem_u[];
    unsigned* s_re = smem_u;             // 8192 x 4B = 32KB
    unsigned* s_im = smem_u + CHUNK;     // 32KB
    __shared__ u64 sg[13][3];            // RY coefs, wires 5..17 -> [w-5]
    __shared__ float2 Plo[64];           // phase for bits 0..5 (wires 17..12)
    __shared__ float2 Phi[128];          // phase for bits 6..12 + chunk phase
    int tid = threadIdx.x;

    int b = blockIdx.x >> 5;
    int H = blockIdx.x & 31;

    if (tid < 13) {
        float ty = params[(layer * 2) * NUM_WIRES + (5 + tid)] * 0.5f;
        float sy, cy; sincosf(ty, &sy, &cy);
        sg[tid][0] = pk2(cy); sg[tid][1] = pk2(sy); sg[tid][2] = pk2(-sy);
    }
    if (!LAST && tid >= 32 && tid < 224) {
        int i = tid - 32;
        const float* tz = params + (layer * 2 + 1) * NUM_WIRES;
        if (i < 64) {
            float ang = 0.0f;
#pragma unroll
            for (int bb = 0; bb < 6; ++bb) {
                float h = tz[17 - bb] * 0.5f;
                ang += ((i >> bb) & 1) ? h : -h;
            }
            float sv, cv; sincosf(ang, &sv, &cv);
            Plo[i] = make_float2(cv, sv);
        } else {
            int hv = i - 64;
            float ang = 0.0f;
#pragma unroll
            for (int w = 0; w < 5; ++w) {           // chunk-const high-wire RZ
                float h = tz[w] * 0.5f;
                ang += ((H >> (4 - w)) & 1) ? h : -h;
            }
#pragma unroll
            for (int bb = 6; bb <= 12; ++bb) {
                float h = tz[17 - bb] * 0.5f;
                ang += ((hv >> (bb - 6)) & 1) ? h : -h;
            }
            float sv, cv; sincosf(ang, &sv, &cv);
            Phi[hv] = make_float2(cv, sv);
        }
    }

    long base = (long)b * DIM + ((long)H << CHUNK_BITS);

    // fill + fused bits 0..3 stage (wires 17..14): thread owns 16 consecutive
    // elements (4 x uint4 per plane).
    {
        const uint4* irr = (const uint4*)(ire + base);
        const uint4* iii = (const uint4*)(iim + base);
        uint4 vr[4], vi[4];
#pragma unroll
        for (int k = 0; k < 4; ++k) { vr[k] = irr[4 * tid + k]; vi[k] = iii[4 * tid + k]; }
        // coefficients must be visible before use
        __syncthreads();
        int t0 = tid << 4;
        // re plane
        {
            u64 x[16];
#pragma unroll
            for (int k = 0; k < 4; ++k) {
                x[4 * k]     = h2u_pk(vr[k].x);
                x[4 * k + 1] = h2u_pk(vr[k].y);
                x[4 * k + 2] = h2u_pk(vr[k].z);
                x[4 * k + 3] = h2u_pk(vr[k].w);
            }
#pragma unroll
            for (int p = 0; p < 4; ++p) {
                u64 c = sg[12 - p][0], s = sg[12 - p][1], ns = sg[12 - p][2];
                int m = 1 << p;
#pragma unroll
                for (int j = 0; j < 16; ++j)
                    if (!(j & m)) ry1(x[j], x[j | m], c, s, ns);
            }
#pragma unroll
            for (int j = 0; j < 16; ++j) s_re[SWX(t0 + j)] = pk2hu(x[j]);
        }
        // im plane
        {
            u64 x[16];
#pragma unroll
            for (int k = 0; k < 4; ++k) {
                x[4 * k]     = h2u_pk(vi[k].x);
                x[4 * k + 1] = h2u_pk(vi[k].y);
                x[4 * k + 2] = h2u_pk(vi[k].z);
                x[4 * k + 3] = h2u_pk(vi[k].w);
            }
#pragma unroll
            for (int p = 0; p < 4; ++p) {
                u64 c = sg[12 - p][0], s = sg[12 - p][1], ns = sg[12 - p][2];
                int m = 1 << p;
#pragma unroll
                for (int j = 0; j < 16; ++j)
                    if (!(j & m)) ry1(x[j], x[j | m], c, s, ns);
            }
#pragma unroll
            for (int j = 0; j < 16; ++j) s_im[SWX(t0 + j)] = pk2hu(x[j]);
        }
    }
    __syncthreads();

    // stage A: bits 4..7 (wires 13..10). Bank-safe map (group bits 0-3,8-12).
    {
        int w = tid >> 5;
        int bs = (tid & 15) | ((w & 1) << 8) | (((tid >> 4) & 1) << 9) | ((w >> 1) << 10);
        stage4p(s_re, sg, bs, 4, 8);
        stage4p(s_im, sg, bs, 4, 8);
    }
    __syncthreads();

    // stage B: bits 8..11 (wires 9..6). Group bits 0-7, 12.
    {
        int bs = (tid & 255) | ((tid >> 8) << 12);
        stage4p(s_re, sg, bs, 8, 4);
        stage4p(s_im, sg, bs, 8, 4);
    }
    __syncthreads();

    // wire 5 (bit 12) RY + diagonal RZ + CNOT-ladder permutation
    int pm = (__popc(H) & 1) ? (CHUNK - 1) : 0;
    int Hd = H ^ (H >> 1); Hd ^= Hd >> 2; Hd ^= Hd >> 4;   // invgray5
    u64 c5 = sg[0][0], s5 = sg[0][1], ns5 = sg[0][2];

    if (!LAST) {
        long obase = (long)b * DIM + ((long)Hd << CHUNK_BITS);
        __half2* dre = ore + obase;
        __half2* dim = oim + obase;
#pragma unroll
        for (int k = 0; k < 4; ++k) {
            int t = 2 * (tid + k * PL_THREADS);     // even, [0,4096)
            int uu = t + 4096;
            u64 rt = h2u_pk(s_re[SWX(t)]),       it = h2u_pk(s_im[SWX(t)]);
            u64 rt1 = h2u_pk(s_re[SWX(t + 1)]),  it1 = h2u_pk(s_im[SWX(t + 1)]);
            u64 ru = h2u_pk(s_re[SWX(uu)]),      iu = h2u_pk(s_im[SWX(uu)]);
            u64 ru1 = h2u_pk(s_re[SWX(uu + 1)]), iu1 = h2u_pk(s_im[SWX(uu + 1)]);
            ry1(rt, ru, c5, s5, ns5);   ry1(it, iu, c5, s5, ns5);
            ry1(rt1, ru1, c5, s5, ns5); ry1(it1, iu1, c5, s5, ns5);
            float2 lo0 = Plo[t & 63], lo1 = Plo[(t & 63) | 1];
            float2 hT = Phi[t >> 6], hU = Phi[(t >> 6) + 64];
            capply(rt, it, cmulf(lo0, hT));   capply(rt1, it1, cmulf(lo1, hT));
            capply(ru, iu, cmulf(lo0, hU));   capply(ru1, iu1, cmulf(lo1, hU));
            int q = invgray(t) ^ pm;
            int qu = q ^ 8191;                      // invgray(4096)=8191
            st_pair(dre, q, rt, rt1);  st_pair(dim, q, it, it1);
            st_pair(dre, qu, ru, ru1); st_pair(dim, qu, iu, iu1);
        }
    } else {
        float a0[NUM_WIRES], a1[NUM_WIRES];
#pragma unroll
        for (int w = 0; w < NUM_WIRES; ++w) { a0[w] = 0.0f; a1[w] = 0.0f; }
        int hi = Hd << CHUNK_BITS;
#pragma unroll
        for (int k = 0; k < 4; ++k) {
            int t = 2 * (tid + k * PL_THREADS);
            int uu = t + 4096;
            u64 rt = h2u_pk(s_re[SWX(t)]),       it = h2u_pk(s_im[SWX(t)]);
            u64 rt1 = h2u_pk(s_re[SWX(t + 1)]),  it1 = h2u_pk(s_im[SWX(t + 1)]);
            u64 ru = h2u_pk(s_re[SWX(uu)]),      iu = h2u_pk(s_im[SWX(uu)]);
            u64 ru1 = h2u_pk(s_re[SWX(uu + 1)]), iu1 = h2u_pk(s_im[SWX(uu + 1)]);
            ry1(rt, ru, c5, s5, ns5);   ry1(it, iu, c5, s5, ns5);
            ry1(rt1, ru1, c5, s5, ns5); ry1(it1, iu1, c5, s5, ns5);
            int q = invgray(t) ^ pm;
            int qu = q ^ 8191;
            float2 pt  = up(fma2(rt, rt, mul2(it, it)));
            float2 pt1 = up(fma2(rt1, rt1, mul2(it1, it1)));
            float2 pu  = up(fma2(ru, ru, mul2(iu, iu)));
            float2 pu1 = up(fma2(ru1, ru1, mul2(iu1, iu1)));
            {
                int d = hi | q;
                unsigned bb0 = __float_as_uint(pt.x + pt1.x);
                unsigned bb1 = __float_as_uint(pt.y + pt1.y);
#pragma unroll
                for (int w = 0; w < 17; ++w) {
                    unsigned bit = (unsigned)(d >> (17 - w)) & 1u;
                    a0[w] += __uint_as_float(bb0 ^ (bit << 31));
                    a1[w] += __uint_as_float(bb1 ^ (bit << 31));
                }
                float d0 = pt.x - pt1.x, d1 = pt.y - pt1.y;
                a0[17] += (q & 1) ? -d0 : d0;
                a1[17] += (q & 1) ? -d1 : d1;
            }
            {
                int d = hi | qu;
                unsigned bb0 = __float_as_uint(pu.x + pu1.x);
                unsigned bb1 = __float_as_uint(pu.y + pu1.y);
#pragma unroll
                for (int w = 0; w < 17; ++w) {
                    unsigned bit = (unsigned)(d >> (17 - w)) & 1u;
                    a0[w] += __uint_as_float(bb0 ^ (bit << 31));
                    a1[w] += __uint_as_float(bb1 ^ (bit << 31));
                }
                float d0 = pu.x - pu1.x, d1 = pu.y - pu1.y;
                a0[17] += (qu & 1) ? -d0 : d0;
                a1[17] += (qu & 1) ? -d1 : d1;
            }
        }
#pragma unroll
        for (int w = 0; w < NUM_WIRES; ++w)
#pragma unroll
            for (int o = 16; o; o >>= 1) {
                a0[w] += __shfl_down_sync(0xFFFFFFFFu, a0[w], o);
                a1[w] += __shfl_down_sync(0xFFFFFFFFu, a1[w], o);
            }
        __syncthreads();
        float* scratch = (float*)smem_u;
        int warp = tid >> 5, lane = tid & 31;
        if (lane == 0) {
#pragma unroll
            for (int w = 0; w < NUM_WIRES; ++w) {
                scratch[(warp * 2 + 0) * NUM_WIRES + w] = a0[w];
                scratch[(warp * 2 + 1) * NUM_WIRES + w] = a1[w];
            }
        }
        __syncthreads();
        if (tid < 2 * NUM_WIRES) {
            int s = tid / NUM_WIRES, w = tid % NUM_WIRES;
            float sum = 0.0f;
#pragma unroll
            for (int k = 0; k < PL_THREADS / 32; ++k)
                sum += scratch[(k * 2 + s) * NUM_WIRES + w];
            partial[(((long)(2 * b + s)) * NCHUNK + H) * NUM_WIRES + w] = sum;
        }
    }
}

__global__ void k_head(const float* __restrict__ head_w,
                       const float* __restrict__ head_b,
                       float* __restrict__ out) {
    int b = threadIdx.x;
    if (b < BATCH) {
        float s = head_b[0];
#pragma unroll
        for (int w = 0; w < NUM_WIRES; ++w) {
            float f = 0.0f;
#pragma unroll
            for (int c = 0; c < NCHUNK; ++c)
                f += g_partial[((long)b * NCHUNK + c) * NUM_WIRES + w];
            s = fmaf(f, head_w[w], s);
        }
        out[b] = s;
    }
}

extern "C" void kernel_launch(void* const* d_in, const int* in_sizes, int n_in,
                              void* d_out, int out_size) {
    const float* state_re = (const float*)d_in[0];
    const float* state_im = (const float*)d_in[1];
    const float* params   = (const float*)d_in[2];
    const float* head_w   = (const float*)d_in[3];
    const float* head_b   = (const float*)d_in[4];
    float* out = (float*)d_out;

    const int shmem = 2 * CHUNK * (int)sizeof(unsigned);   // 64KB
    cudaFuncSetAttribute(k_pass_low<0>, cudaFuncAttributeMaxDynamicSharedMemorySize, shmem);
    cudaFuncSetAttribute(k_pass_low<1>, cudaFuncAttributeMaxDynamicSharedMemorySize, shmem);

    static __half2 *re0 = nullptr, *im0 = nullptr, *re1 = nullptr, *im1 = nullptr;
    static float* ptp = nullptr;
    if (!re0) {
        cudaGetSymbolAddress((void**)&re0, g_re0);
        cudaGetSymbolAddress((void**)&im0, g_im0);
        cudaGetSymbolAddress((void**)&re1, g_re1);
        cudaGetSymbolAddress((void**)&im1, g_im1);
        cudaGetSymbolAddress((void**)&ptp, g_partial);
    }

    const int ph_blocks = (GP * 2 * CHUNK) / PH_THREADS;   // 1024
    const int pl_blocks = GP * NCHUNK;                     // 512

    // L2-resident groups of GP=16 pairs (working set 67MB < L2)
    for (int grp = 0; grp < NPAIR / GP; ++grp) {
        long poff = (long)grp * GP * DIM;       // pair-plane offset
        long soff = (long)grp * GP * 2 * DIM;   // fp32 input offset
        __half2 *r0 = re0 + poff, *i0 = im0 + poff;
        __half2 *r1 = re1 + poff, *i1 = im1 + poff;
        float* part = ptp + (long)grp * GP * 2 * NCHUNK * NUM_WIRES;

        // layer 0
        k_first<<<ph_blocks, PH_THREADS>>>(state_re + soff, state_im + soff, r0, i0, params);
        k_pass_low<0><<<pl_blocks, PL_THREADS, shmem>>>(r0, i0, r1, i1, params, part, 0);
        // layer 1
        k_pass_high<<<ph_blocks, PH_THREADS>>>(r1, i1, params, 1);
        k_pass_low<0><<<pl_blocks, PL_THREADS, shmem>>>(r1, i1, r0, i0, params, part, 1);
        // layer 2
        k_pass_high<<<ph_blocks, PH_THREADS>>>(r0, i0, params, 2);
        k_pass_low<1><<<pl_blocks, PL_THREADS, shmem>>>(r0, i0, r1, i1, params, part, 2);
    }

    k_head<<<1, 64>>>(head_w, head_b, out);
}

// round 14
// speedup vs baseline: 1.2375x; 1.2375x over previous
#include <cuda_runtime.h>
#include <cuda_fp16.h>
#include <math.h>

#define NUM_WIRES 18
#define BATCH     64
#define NPAIR     32
#define GP        16               // pairs per L2-resident group (2 groups)
#define DIM       262144           // 2^18
#define CHUNK_BITS 13
#define CHUNK     8192
#define NCHUNK    32
#define PL_THREADS 512
#define PH_THREADS 256

typedef unsigned long long u64;
typedef __half2 h2;

// SoA component planes; each half2 = (state_s0, state_s1)
__device__ __half2 g_re0[NPAIR * DIM];
__device__ __half2 g_im0[NPAIR * DIM];
__device__ __half2 g_re1[NPAIR * DIM];
__device__ __half2 g_im1[NPAIR * DIM];
__device__ float g_partial[BATCH * NCHUNK * NUM_WIRES];

// ---- packed f32x2 primitives (k_first only) ----
__device__ __forceinline__ u64 pk(float lo, float hi) {
    u64 r; asm("mov.b64 %0,{%1,%2};" : "=l"(r) : "f"(lo), "f"(hi)); return r;
}
__device__ __forceinline__ u64 pk2(float x) { return pk(x, x); }
__device__ __forceinline__ float2 up(u64 v) {
    float2 f; asm("mov.b64 {%0,%1},%2;" : "=f"(f.x), "=f"(f.y) : "l"(v)); return f;
}
__device__ __forceinline__ u64 fma2(u64 a, u64 b, u64 c) {
    u64 d; asm("fma.rn.f32x2 %0,%1,%2,%3;" : "=l"(d) : "l"(a), "l"(b), "l"(c)); return d;
}
__device__ __forceinline__ u64 mul2(u64 a, u64 b) {
    u64 d; asm("mul.rn.f32x2 %0,%1,%2;" : "=l"(d) : "l"(a), "l"(b)); return d;
}
__device__ __forceinline__ unsigned pk2hu(u64 v) {
    float2 f = up(v); __half2 h = __floats2half2_rn(f.x, f.y); return *(unsigned*)&h;
}
__device__ __forceinline__ void ry1(u64& a, u64& b, u64 c, u64 s, u64 ns) {
    u64 na = fma2(c, a, mul2(ns, b));
    b = fma2(s, a, mul2(c, b));
    a = na;
}

// ---- half2 primitives (main compute path) ----
__device__ __forceinline__ h2 u2h(unsigned u) { h2 h; *(unsigned*)&h = u; return h; }
__device__ __forceinline__ unsigned h2u(h2 h) { return *(unsigned*)&h; }
// real RY butterfly in half2 (2 states SIMD)
__device__ __forceinline__ void ry1h(h2& a, h2& b, h2 c, h2 s, h2 ns) {
    h2 na = __hfma2(c, a, __hmul2(ns, b));
    b = __hfma2(s, a, __hmul2(c, b));
    a = na;
}
// complex phase multiply in half2 (phase given in fp32)
__device__ __forceinline__ void capply_h(h2& r, h2& i, float2 p) {
    h2 pr = __float2half2_rn(p.x), pi = __float2half2_rn(p.y), npi = __float2half2_rn(-p.y);
    h2 nr = __hfma2(pr, r, __hmul2(npi, i));
    i = __hfma2(pr, i, __hmul2(pi, r));
    r = nr;
}
__device__ __forceinline__ float2 cmulf(float2 a, float2 b) {
    return make_float2(a.x * b.x - a.y * b.y, a.x * b.y + a.y * b.x);
}

// fold-XOR swizzle on 4B-word index: bank bit i = e_i ^ e_{i+5} ^ e_{i+10}
__device__ __forceinline__ int SWX(int e) { return e ^ ((e >> 5) & 31) ^ ((e >> 10) & 31); }
__device__ __forceinline__ int invgray(int t) {
    t ^= t >> 1; t ^= t >> 2; t ^= t >> 4; t ^= t >> 8; return t;
}
__device__ __forceinline__ void st_pair(__half2* pl, int q, unsigned va, unsigned vb) {
    uint2 o; o.x = (q & 1) ? vb : va; o.y = (q & 1) ? va : vb;
    *(uint2*)(pl + (q & ~1)) = o;
}

// ---------------------------------------------------------------------------
// pass_high: RY-only, wires 0..4 (bits 17..13), per component plane, in place.
// half2 compute: 32 regs of data, no conversions.
// ---------------------------------------------------------------------------
__global__ void __launch_bounds__(PH_THREADS, 4)
k_pass_high(__half2* __restrict__ bre, __half2* __restrict__ bim,
            const float* __restrict__ params, int layer) {
    int gid = blockIdx.x * PH_THREADS + threadIdx.x;
    int u = gid & (CHUNK - 1);
    int r = gid >> CHUNK_BITS;
    __half2* pl = ((r & 1) ? bim : bre) + (long)(r >> 1) * DIM + u;

    h2 x[32];
#pragma unroll
    for (int j = 0; j < 32; ++j) x[j] = pl[(long)j << CHUNK_BITS];

#pragma unroll
    for (int w = 0; w < 5; ++w) {
        float ty = params[(layer * 2) * NUM_WIRES + w] * 0.5f;
        float sy, cy; sincosf(ty, &sy, &cy);
        h2 c = __float2half2_rn(cy), s = __float2half2_rn(sy), ns = __float2half2_rn(-sy);
        int m = 16 >> w;
#pragma unroll
        for (int j = 0; j < 32; ++j)
            if (!(j & m)) ry1h(x[j], x[j | m], c, s, ns);
    }
#pragma unroll
    for (int j = 0; j < 32; ++j) pl[(long)j << CHUNK_BITS] = x[j];
}

// layer-0 variant: fp32 inputs (rows 2p, 2p+1), fp32 math, writes half2 planes
__global__ void __launch_bounds__(PH_THREADS, 2)
k_first(const float* __restrict__ sre, const float* __restrict__ sim,
        __half2* __restrict__ ore, __half2* __restrict__ oim,
        const float* __restrict__ params) {
    int gid = blockIdx.x * PH_THREADS + threadIdx.x;
    int u = gid & (CHUNK - 1);
    int r = gid >> CHUNK_BITS;
    int c = r & 1, p = r >> 1;
    const float* src = c ? sim : sre;
    const float* r0 = src + (long)(2 * p) * DIM + u;
    const float* r1 = src + (long)(2 * p + 1) * DIM + u;

    u64 x[32];
#pragma unroll
    for (int j = 0; j < 32; ++j)
        x[j] = pk(r0[(long)j << CHUNK_BITS], r1[(long)j << CHUNK_BITS]);
#pragma unroll
    for (int w = 0; w < 5; ++w) {
        float ty = params[w] * 0.5f;
        float sy, cy; sincosf(ty, &sy, &cy);
        u64 cc = pk2(cy), s = pk2(sy), ns = pk2(-sy);
        int m = 16 >> w;
#pragma unroll
        for (int j = 0; j < 32; ++j)
            if (!(j & m)) ry1(x[j], x[j | m], cc, s, ns);
    }
    __half2* pl = (c ? oim : ore) + (long)p * DIM + u;
#pragma unroll
    for (int j = 0; j < 32; ++j)
        *(unsigned*)(pl + ((long)j << CHUNK_BITS)) = pk2hu(x[j]);
}

// 4-bit RY stage on ONE plane in half2: 16 values per group, bit offset sh.
__device__ __forceinline__ void stage4h(unsigned* pl, const h2 (*sg)[3],
                                        int base, int sh, int wi0) {
    h2 x[16];
#pragma unroll
    for (int j = 0; j < 16; ++j) x[j] = u2h(pl[SWX(base | (j << sh))]);
#pragma unroll
    for (int p = 0; p < 4; ++p) {
        h2 c = sg[wi0 - p][0], s = sg[wi0 - p][1], ns = sg[wi0 - p][2];
        int m = 1 << p;
#pragma unroll
        for (int j = 0; j < 16; ++j)
            if (!(j & m)) ry1h(x[j], x[j | m], c, s, ns);
    }
#pragma unroll
    for (int j = 0; j < 16; ++j) pl[SWX(base | (j << sh))] = h2u(x[j]);
}

// ---------------------------------------------------------------------------
// pass_low: wires 5..17 (bits 12..0); fp16 smem + half2 compute (no convs).
// Fill fuses the bits 0..3 stage (wires 17..14); two 4-bit smem stages;
// wire 5 (bit 12) + diagonal RZ phase fused with Gray scatter.
// LAST: expectation values (fp32 accumulation), no RZ.
// ---------------------------------------------------------------------------
template <int LAST>
__global__ void __launch_bounds__(PL_THREADS, 2)
k_pass_low(const __half2* __restrict__ ire, const __half2* __restrict__ iim,
           __half2* __restrict__ ore, __half2* __restrict__ oim,
           const float* __restrict__ params, float* __restrict__ partial,
           int layer) {
    extern __shared__ unsigned smem_u[];
    unsigned* s_re = smem_u;             // 8192 x 4B = 32KB
    unsigned* s_im = smem_u + CHUNK;     // 32KB
    __shared__ h2 sg[13][3];             // RY coefs, wires 5..17 -> [w-5]
    __shared__ float2 Plo[64];           // phase for bits 0..5 (wires 17..12)
    __shared__ float2 Phi[128];          // phase for bits 6..12 + chunk phase
    int tid = threadIdx.x;

    int b = blockIdx.x >> 5;
    int H = blockIdx.x & 31;

    if (tid < 13) {
        float ty = params[(layer * 2) * NUM_WIRES + (5 + tid)] * 0.5f;
        float sy, cy; sincosf(ty, &sy, &cy);
        sg[tid][0] = __float2half2_rn(cy);
        sg[tid][1] = __float2half2_rn(sy);
        sg[tid][2] = __float2half2_rn(-sy);
    }
    if (!LAST && tid >= 32 && tid < 224) {
        int i = tid - 32;
        const float* tz = params + (layer * 2 + 1) * NUM_WIRES;
        if (i < 64) {
            float ang = 0.0f;
#pragma unroll
            for (int bb = 0; bb < 6; ++bb) {
                float h = tz[17 - bb] * 0.5f;
                ang += ((i >> bb) & 1) ? h : -h;
            }
            float sv, cv; sincosf(ang, &sv, &cv);
            Plo[i] = make_float2(cv, sv);
        } else {
            int hv = i - 64;
            float ang = 0.0f;
#pragma unroll
            for (int w = 0; w < 5; ++w) {           // chunk-const high-wire RZ
                float h = tz[w] * 0.5f;
                ang += ((H >> (4 - w)) & 1) ? h : -h;
            }
#pragma unroll
            for (int bb = 6; bb <= 12; ++bb) {
                float h = tz[17 - bb] * 0.5f;
                ang += ((hv >> (bb - 6)) & 1) ? h : -h;
            }
            float sv, cv; sincosf(ang, &sv, &cv);
            Phi[hv] = make_float2(cv, sv);
        }
    }

    long base = (long)b * DIM + ((long)H << CHUNK_BITS);

    // fill + fused bits 0..3 stage (wires 17..14), half2 end-to-end
    {
        const uint4* irr = (const uint4*)(ire + base);
        const uint4* iii = (const uint4*)(iim + base);
        uint4 vr[4], vi[4];
#pragma unroll
        for (int k = 0; k < 4; ++k) { vr[k] = irr[4 * tid + k]; vi[k] = iii[4 * tid + k]; }
        __syncthreads();                  // sg/Plo/Phi visible
        int t0 = tid << 4;
        {
            h2 x[16];
#pragma unroll
            for (int k = 0; k < 4; ++k) {
                x[4 * k]     = u2h(vr[k].x);
                x[4 * k + 1] = u2h(vr[k].y);
                x[4 * k + 2] = u2h(vr[k].z);
                x[4 * k + 3] = u2h(vr[k].w);
            }
#pragma unroll
            for (int p = 0; p < 4; ++p) {
                h2 c = sg[12 - p][0], s = sg[12 - p][1], ns = sg[12 - p][2];
                int m = 1 << p;
#pragma unroll
                for (int j = 0; j < 16; ++j)
                    if (!(j & m)) ry1h(x[j], x[j | m], c, s, ns);
            }
#pragma unroll
            for (int j = 0; j < 16; ++j) s_re[SWX(t0 + j)] = h2u(x[j]);
        }
        {
            h2 x[16];
#pragma unroll
            for (int k = 0; k < 4; ++k) {
                x[4 * k]     = u2h(vi[k].x);
                x[4 * k + 1] = u2h(vi[k].y);
                x[4 * k + 2] = u2h(vi[k].z);
                x[4 * k + 3] = u2h(vi[k].w);
            }
#pragma unroll
            for (int p = 0; p < 4; ++p) {
                h2 c = sg[12 - p][0], s = sg[12 - p][1], ns = sg[12 - p][2];
                int m = 1 << p;
#pragma unroll
                for (int j = 0; j < 16; ++j)
                    if (!(j & m)) ry1h(x[j], x[j | m], c, s, ns);
            }
#pragma unroll
            for (int j = 0; j < 16; ++j) s_im[SWX(t0 + j)] = h2u(x[j]);
        }
    }
    __syncthreads();

    // stage A: bits 4..7 (wires 13..10). Bank-safe map.
    {
        int w = tid >> 5;
        int bs = (tid & 15) | ((w & 1) << 8) | (((tid >> 4) & 1) << 9) | ((w >> 1) << 10);
        stage4h(s_re, sg, bs, 4, 8);
        stage4h(s_im, sg, bs, 4, 8);
    }
    __syncthreads();

    // stage B: bits 8..11 (wires 9..6). Group bits 0-7, 12.
    {
        int bs = (tid & 255) | ((tid >> 8) << 12);
        stage4h(s_re, sg, bs, 8, 4);
        stage4h(s_im, sg, bs, 8, 4);
    }
    __syncthreads();

    // wire 5 (bit 12) RY + diagonal RZ + CNOT-ladder permutation
    int pm = (__popc(H) & 1) ? (CHUNK - 1) : 0;
    int Hd = H ^ (H >> 1); Hd ^= Hd >> 2; Hd ^= Hd >> 4;   // invgray5
    h2 c5 = sg[0][0], s5 = sg[0][1], ns5 = sg[0][2];

    if (!LAST) {
        long obase = (long)b * DIM + ((long)Hd << CHUNK_BITS);
        __half2* dre = ore + obase;
        __half2* dim = oim + obase;
#pragma unroll
        for (int k = 0; k < 4; ++k) {
            int t = 2 * (tid + k * PL_THREADS);     // even, [0,4096)
            int uu = t + 4096;
            h2 rt = u2h(s_re[SWX(t)]),       it = u2h(s_im[SWX(t)]);
            h2 rt1 = u2h(s_re[SWX(t + 1)]),  it1 = u2h(s_im[SWX(t + 1)]);
            h2 ru = u2h(s_re[SWX(uu)]),      iu = u2h(s_im[SWX(uu)]);
            h2 ru1 = u2h(s_re[SWX(uu + 1)]), iu1 = u2h(s_im[SWX(uu + 1)]);
            ry1h(rt, ru, c5, s5, ns5);   ry1h(it, iu, c5, s5, ns5);
            ry1h(rt1, ru1, c5, s5, ns5); ry1h(it1, iu1, c5, s5, ns5);
            float2 lo0 = Plo[t & 63], lo1 = Plo[(t & 63) | 1];
            float2 hT = Phi[t >> 6], hU = Phi[(t >> 6) + 64];
            capply_h(rt, it, cmulf(lo0, hT));   capply_h(rt1, it1, cmulf(lo1, hT));
            capply_h(ru, iu, cmulf(lo0, hU));   capply_h(ru1, iu1, cmulf(lo1, hU));
            int q = invgray(t) ^ pm;
            int qu = q ^ 8191;                      // invgray(4096)=8191
            st_pair(dre, q, h2u(rt), h2u(rt1));  st_pair(dim, q, h2u(it), h2u(it1));
            st_pair(dre, qu, h2u(ru), h2u(ru1)); st_pair(dim, qu, h2u(iu), h2u(iu1));
        }
    } else {
        float a0[NUM_WIRES], a1[NUM_WIRES];
#pragma unroll
        for (int w = 0; w < NUM_WIRES; ++w) { a0[w] = 0.0f; a1[w] = 0.0f; }
        int hi = Hd << CHUNK_BITS;
#pragma unroll
        for (int k = 0; k < 4; ++k) {
            int t = 2 * (tid + k * PL_THREADS);
            int uu = t + 4096;
            h2 rt = u2h(s_re[SWX(t)]),       it = u2h(s_im[SWX(t)]);
            h2 rt1 = u2h(s_re[SWX(t + 1)]),  it1 = u2h(s_im[SWX(t + 1)]);
            h2 ru = u2h(s_re[SWX(uu)]),      iu = u2h(s_im[SWX(uu)]);
            h2 ru1 = u2h(s_re[SWX(uu + 1)]), iu1 = u2h(s_im[SWX(uu + 1)]);
            ry1h(rt, ru, c5, s5, ns5);   ry1h(it, iu, c5, s5, ns5);
            ry1h(rt1, ru1, c5, s5, ns5); ry1h(it1, iu1, c5, s5, ns5);
            int q = invgray(t) ^ pm;
            int qu = q ^ 8191;
            float2 frt = __half22float2(rt),   fit = __half22float2(it);
            float2 frt1 = __half22float2(rt1), fit1 = __half22float2(it1);
            float2 fru = __half22float2(ru),   fiu = __half22float2(iu);
            float2 fru1 = __half22float2(ru1), fiu1 = __half22float2(iu1);
            float2 pt  = make_float2(frt.x * frt.x + fit.x * fit.x,
                                     frt.y * frt.y + fit.y * fit.y);
            float2 pt1 = make_float2(frt1.x * frt1.x + fit1.x * fit1.x,
                                     frt1.y * frt1.y + fit1.y * fit1.y);
            float2 pu  = make_float2(fru.x * fru.x + fiu.x * fiu.x,
                                     fru.y * fru.y + fiu.y * fiu.y);
            float2 pu1 = make_float2(fru1.x * fru1.x + fiu1.x * fiu1.x,
                                     fru1.y * fru1.y + fiu1.y * fiu1.y);
            {
                int d = hi | q;
                unsigned bb0 = __float_as_uint(pt.x + pt1.x);
                unsigned bb1 = __float_as_uint(pt.y + pt1.y);
#pragma unroll
                for (int w = 0; w < 17; ++w) {
                    unsigned bit = (unsigned)(d >> (17 - w)) & 1u;
                    a0[w] += __uint_as_float(bb0 ^ (bit << 31));
                    a1[w] += __uint_as_float(bb1 ^ (bit << 31));
                }
                float d0 = pt.x - pt1.x, d1 = pt.y - pt1.y;
                a0[17] += (q & 1) ? -d0 : d0;
                a1[17] += (q & 1) ? -d1 : d1;
            }
            {
                int d = hi | qu;
                unsigned bb0 = __float_as_uint(pu.x + pu1.x);
                unsigned bb1 = __float_as_uint(pu.y + pu1.y);
#pragma unroll
                for (int w = 0; w < 17; ++w) {
                    unsigned bit = (unsigned)(d >> (17 - w)) & 1u;
                    a0[w] += __uint_as_float(bb0 ^ (bit << 31));
                    a1[w] += __uint_as_float(bb1 ^ (bit << 31));
                }
                float d0 = pu.x - pu1.x, d1 = pu.y - pu1.y;
                a0[17] += (qu & 1) ? -d0 : d0;
                a1[17] += (qu & 1) ? -d1 : d1;
            }
        }
#pragma unroll
        for (int w = 0; w < NUM_WIRES; ++w)
#pragma unroll
            for (int o = 16; o; o >>= 1) {
                a0[w] += __shfl_down_sync(0xFFFFFFFFu, a0[w], o);
                a1[w] += __shfl_down_sync(0xFFFFFFFFu, a1[w], o);
            }
        __syncthreads();
        float* scratch = (float*)smem_u;
        int warp = tid >> 5, lane = tid & 31;
        if (lane == 0) {
#pragma unroll
            for (int w = 0; w < NUM_WIRES; ++w) {
                scratch[(warp * 2 + 0) * NUM_WIRES + w] = a0[w];
                scratch[(warp * 2 + 1) * NUM_WIRES + w] = a1[w];
            }
        }
        __syncthreads();
        if (tid < 2 * NUM_WIRES) {
            int s = tid / NUM_WIRES, w = tid % NUM_WIRES;
            float sum = 0.0f;
#pragma unroll
            for (int k = 0; k < PL_THREADS / 32; ++k)
                sum += scratch[(k * 2 + s) * NUM_WIRES + w];
            partial[(((long)(2 * b + s)) * NCHUNK + H) * NUM_WIRES + w] = sum;
        }
    }
}

__global__ void k_head(const float* __restrict__ head_w,
                       const float* __restrict__ head_b,
                       float* __restrict__ out) {
    int b = threadIdx.x;
    if (b < BATCH) {
        float s = head_b[0];
#pragma unroll
        for (int w = 0; w < NUM_WIRES; ++w) {
            float f = 0.0f;
#pragma unroll
            for (int c = 0; c < NCHUNK; ++c)
                f += g_partial[((long)b * NCHUNK + c) * NUM_WIRES + w];
            s = fmaf(f, head_w[w], s);
        }
        out[b] = s;
    }
}

extern "C" void kernel_launch(void* const* d_in, const int* in_sizes, int n_in,
                              void* d_out, int out_size) {
    const float* state_re = (const float*)d_in[0];
    const float* state_im = (const float*)d_in[1];
    const float* params   = (const float*)d_in[2];
    const float* head_w   = (const float*)d_in[3];
    const float* head_b   = (const float*)d_in[4];
    float* out = (float*)d_out;

    const int shmem = 2 * CHUNK * (int)sizeof(unsigned);   // 64KB
    cudaFuncSetAttribute(k_pass_low<0>, cudaFuncAttributeMaxDynamicSharedMemorySize, shmem);
    cudaFuncSetAttribute(k_pass_low<1>, cudaFuncAttributeMaxDynamicSharedMemorySize, shmem);

    static __half2 *re0 = nullptr, *im0 = nullptr, *re1 = nullptr, *im1 = nullptr;
    static float* ptp = nullptr;
    if (!re0) {
        cudaGetSymbolAddress((void**)&re0, g_re0);
        cudaGetSymbolAddress((void**)&im0, g_im0);
        cudaGetSymbolAddress((void**)&re1, g_re1);
        cudaGetSymbolAddress((void**)&im1, g_im1);
        cudaGetSymbolAddress((void**)&ptp, g_partial);
    }

    const int ph_blocks = (GP * 2 * CHUNK) / PH_THREADS;   // 1024
    const int pl_blocks = GP * NCHUNK;                     // 512

    // L2-resident groups of GP=16 pairs (working set 67MB < L2)
    for (int grp = 0; grp < NPAIR / GP; ++grp) {
        long poff = (long)grp * GP * DIM;       // pair-plane offset
        long soff = (long)grp * GP * 2 * DIM;   // fp32 input offset
        __half2 *r0 = re0 + poff, *i0 = im0 + poff;
        __half2 *r1 = re1 + poff, *i1 = im1 + poff;
        float* part = ptp + (long)grp * GP * 2 * NCHUNK * NUM_WIRES;

        // layer 0
        k_first<<<ph_blocks, PH_THREADS>>>(state_re + soff, state_im + soff, r0, i0, params);
        k_pass_low<0><<<pl_blocks, PL_THREADS, shmem>>>(r0, i0, r1, i1, params, part, 0);
        // layer 1
        k_pass_high<<<ph_blocks, PH_THREADS>>>(r1, i1, params, 1);
        k_pass_low<0><<<pl_blocks, PL_THREADS, shmem>>>(r1, i1, r0, i0, params, part, 1);
        // layer 2
        k_pass_high<<<ph_blocks, PH_THREADS>>>(r0, i0, params, 2);
        k_pass_low<1><<<pl_blocks, PL_THREADS, shmem>>>(r0, i0, r1, i1, params, part, 2);
    }

    k_head<<<1, 64>>>(head_w, head_b, out);
}

// round 15
// speedup vs baseline: 1.2440x; 1.0052x over previous
#include <cuda_runtime.h>
#include <cuda_fp16.h>
#include <math.h>

#define NUM_WIRES 18
#define BATCH     64
#define NPAIR     32
#define GP        16               // pairs per L2-resident group (2 groups)
#define DIM       262144           // 2^18
#define CHUNK_BITS 13
#define CHUNK     8192
#define NCHUNK    32
#define PL_THREADS 512
#define PH_THREADS 256

typedef unsigned long long u64;
typedef __half2 h2;

// SoA component planes; each half2 = (state_s0, state_s1)
__device__ __half2 g_re0[NPAIR * DIM];
__device__ __half2 g_im0[NPAIR * DIM];
__device__ __half2 g_re1[NPAIR * DIM];
__device__ __half2 g_im1[NPAIR * DIM];
__device__ float g_partial[BATCH * NCHUNK * NUM_WIRES];

// ---- packed f32x2 primitives (k_first only) ----
__device__ __forceinline__ u64 pk(float lo, float hi) {
    u64 r; asm("mov.b64 %0,{%1,%2};" : "=l"(r) : "f"(lo), "f"(hi)); return r;
}
__device__ __forceinline__ u64 pk2(float x) { return pk(x, x); }
__device__ __forceinline__ float2 up(u64 v) {
    float2 f; asm("mov.b64 {%0,%1},%2;" : "=f"(f.x), "=f"(f.y) : "l"(v)); return f;
}
__device__ __forceinline__ u64 fma2(u64 a, u64 b, u64 c) {
    u64 d; asm("fma.rn.f32x2 %0,%1,%2,%3;" : "=l"(d) : "l"(a), "l"(b), "l"(c)); return d;
}
__device__ __forceinline__ u64 mul2(u64 a, u64 b) {
    u64 d; asm("mul.rn.f32x2 %0,%1,%2;" : "=l"(d) : "l"(a), "l"(b)); return d;
}
__device__ __forceinline__ unsigned pk2hu(u64 v) {
    float2 f = up(v); __half2 h = __floats2half2_rn(f.x, f.y); return *(unsigned*)&h;
}
__device__ __forceinline__ void ry1(u64& a, u64& b, u64 c, u64 s, u64 ns) {
    u64 na = fma2(c, a, mul2(ns, b));
    b = fma2(s, a, mul2(c, b));
    a = na;
}

// ---- half2 primitives (main compute path) ----
__device__ __forceinline__ h2 u2h(unsigned u) { h2 h; *(unsigned*)&h = u; return h; }
__device__ __forceinline__ unsigned h2u(h2 h) { return *(unsigned*)&h; }
// real RY butterfly in half2 (2 states SIMD)
__device__ __forceinline__ void ry1h(h2& a, h2& b, h2 c, h2 s, h2 ns) {
    h2 na = __hfma2(c, a, __hmul2(ns, b));
    b = __hfma2(s, a, __hmul2(c, b));
    a = na;
}
// complex phase multiply in half2 (phase given in fp32)
__device__ __forceinline__ void capply_h(h2& r, h2& i, float2 p) {
    h2 pr = __float2half2_rn(p.x), pi = __float2half2_rn(p.y), npi = __float2half2_rn(-p.y);
    h2 nr = __hfma2(pr, r, __hmul2(npi, i));
    i = __hfma2(pr, i, __hmul2(pi, r));
    r = nr;
}
__device__ __forceinline__ float2 cmulf(float2 a, float2 b) {
    return make_float2(a.x * b.x - a.y * b.y, a.x * b.y + a.y * b.x);
}

// fold-XOR swizzle on 4B-word index: bank bit i = e_i ^ e_{i+5} ^ e_{i+10}
__device__ __forceinline__ int SWX(int e) { return e ^ ((e >> 5) & 31) ^ ((e >> 10) & 31); }
__device__ __forceinline__ int invgray(int t) {
    t ^= t >> 1; t ^= t >> 2; t ^= t >> 4; t ^= t >> 8; return t;
}
__device__ __forceinline__ void st_pair(__half2* pl, int q, unsigned va, unsigned vb) {
    uint2 o; o.x = (q & 1) ? vb : va; o.y = (q & 1) ? va : vb;
    *(uint2*)(pl + (q & ~1)) = o;
}

// ---------------------------------------------------------------------------
// pass_high: RY-only, wires 0..4 (bits 17..13), per component plane, in place.
// half2 compute: 32 regs of data, no conversions.
// ---------------------------------------------------------------------------
__global__ void __launch_bounds__(PH_THREADS, 4)
k_pass_high(__half2* __restrict__ bre, __half2* __restrict__ bim,
            const float* __restrict__ params, int layer) {
    int gid = blockIdx.x * PH_THREADS + threadIdx.x;
    int u = gid & (CHUNK - 1);
    int r = gid >> CHUNK_BITS;
    __half2* pl = ((r & 1) ? bim : bre) + (long)(r >> 1) * DIM + u;

    h2 x[32];
#pragma unroll
    for (int j = 0; j < 32; ++j) x[j] = pl[(long)j << CHUNK_BITS];

#pragma unroll
    for (int w = 0; w < 5; ++w) {
        float ty = params[(layer * 2) * NUM_WIRES + w] * 0.5f;
        float sy, cy; sincosf(ty, &sy, &cy);
        h2 c = __float2half2_rn(cy), s = __float2half2_rn(sy), ns = __float2half2_rn(-sy);
        int m = 16 >> w;
#pragma unroll
        for (int j = 0; j < 32; ++j)
            if (!(j & m)) ry1h(x[j], x[j | m], c, s, ns);
    }
#pragma unroll
    for (int j = 0; j < 32; ++j) pl[(long)j << CHUNK_BITS] = x[j];
}

// layer-0 variant: fp32 inputs (rows 2p, 2p+1), fp32 math, writes half2 planes
__global__ void __launch_bounds__(PH_THREADS, 2)
k_first(const float* __restrict__ sre, const float* __restrict__ sim,
        __half2* __restrict__ ore, __half2* __restrict__ oim,
        const float* __restrict__ params) {
    int gid = blockIdx.x * PH_THREADS + threadIdx.x;
    int u = gid & (CHUNK - 1);
    int r = gid >> CHUNK_BITS;
    int c = r & 1, p = r >> 1;
    const float* src = c ? sim : sre;
    const float* r0 = src + (long)(2 * p) * DIM + u;
    const float* r1 = src + (long)(2 * p + 1) * DIM + u;

    u64 x[32];
#pragma unroll
    for (int j = 0; j < 32; ++j)
        x[j] = pk(r0[(long)j << CHUNK_BITS], r1[(long)j << CHUNK_BITS]);
#pragma unroll
    for (int w = 0; w < 5; ++w) {
        float ty = params[w] * 0.5f;
        float sy, cy; sincosf(ty, &sy, &cy);
        u64 cc = pk2(cy), s = pk2(sy), ns = pk2(-sy);
        int m = 16 >> w;
#pragma unroll
        for (int j = 0; j < 32; ++j)
            if (!(j & m)) ry1(x[j], x[j | m], cc, s, ns);
    }
    __half2* pl = (c ? oim : ore) + (long)p * DIM + u;
#pragma unroll
    for (int j = 0; j < 32; ++j)
        *(unsigned*)(pl + ((long)j << CHUNK_BITS)) = pk2hu(x[j]);
}

// 4-bit RY stage on ONE plane in half2: 16 values per group, bit offset sh.
__device__ __forceinline__ void stage4h(unsigned* pl, const h2 (*sg)[3],
                                        int base, int sh, int wi0) {
    h2 x[16];
#pragma unroll
    for (int j = 0; j < 16; ++j) x[j] = u2h(pl[SWX(base | (j << sh))]);
#pragma unroll
    for (int p = 0; p < 4; ++p) {
        h2 c = sg[wi0 - p][0], s = sg[wi0 - p][1], ns = sg[wi0 - p][2];
        int m = 1 << p;
#pragma unroll
        for (int j = 0; j < 16; ++j)
            if (!(j & m)) ry1h(x[j], x[j | m], c, s, ns);
    }
#pragma unroll
    for (int j = 0; j < 16; ++j) pl[SWX(base | (j << sh))] = h2u(x[j]);
}

// ---------------------------------------------------------------------------
// pass_low: wires 5..17 (bits 12..0); fp16 smem + half2 compute (no convs).
// Fill fuses the bits 0..3 stage (wires 17..14); two 4-bit smem stages;
// wire 5 (bit 12) + diagonal RZ phase fused with Gray scatter.
// LAST: expectation values (fp32 accumulation), no RZ.
// ---------------------------------------------------------------------------
template <int LAST>
__global__ void __launch_bounds__(PL_THREADS, 2)
k_pass_low(const __half2* __restrict__ ire, const __half2* __restrict__ iim,
           __half2* __restrict__ ore, __half2* __restrict__ oim,
           const float* __restrict__ params, float* __restrict__ partial,
           int layer) {
    extern __shared__ unsigned smem_u[];
    unsigned* s_re = smem_u;             // 8192 x 4B = 32KB
    unsigned* s_im = smem_u + CHUNK;     // 32KB
    __shared__ h2 sg[13][3];             // RY coefs, wires 5..17 -> [w-5]
    __shared__ float2 Plo[64];           // phase for bits 0..5 (wires 17..12)
    __shared__ float2 Phi[128];          // phase for bits 6..12 + chunk phase
    int tid = threadIdx.x;

    int b = blockIdx.x >> 5;
    int H = blockIdx.x & 31;

    if (tid < 13) {
        float ty = params[(layer * 2) * NUM_WIRES + (5 + tid)] * 0.5f;
        float sy, cy; sincosf(ty, &sy, &cy);
        sg[tid][0] = __float2half2_rn(cy);
        sg[tid][1] = __float2half2_rn(sy);
        sg[tid][2] = __float2half2_rn(-sy);
    }
    if (!LAST && tid >= 32 && tid < 224) {
        int i = tid - 32;
        const float* tz = params + (layer * 2 + 1) * NUM_WIRES;
        if (i < 64) {
            float ang = 0.0f;
#pragma unroll
            for (int bb = 0; bb < 6; ++bb) {
                float h = tz[17 - bb] * 0.5f;
                ang += ((i >> bb) & 1) ? h : -h;
            }
            float sv, cv; sincosf(ang, &sv, &cv);
            Plo[i] = make_float2(cv, sv);
        } else {
            int hv = i - 64;
            float ang = 0.0f;
#pragma unroll
            for (int w = 0; w < 5; ++w) {           // chunk-const high-wire RZ
                float h = tz[w] * 0.5f;
                ang += ((H >> (4 - w)) & 1) ? h : -h;
            }
#pragma unroll
            for (int bb = 6; bb <= 12; ++bb) {
                float h = tz[17 - bb] * 0.5f;
                ang += ((hv >> (bb - 6)) & 1) ? h : -h;
            }
            float sv, cv; sincosf(ang, &sv, &cv);
            Phi[hv] = make_float2(cv, sv);
        }
    }

    long base = (long)b * DIM + ((long)H << CHUNK_BITS);

    // fill + fused bits 0..3 stage (wires 17..14), half2 end-to-end
    {
        const uint4* irr = (const uint4*)(ire + base);
        const uint4* iii = (const uint4*)(iim + base);
        uint4 vr[4], vi[4];
#pragma unroll
        for (int k = 0; k < 4; ++k) { vr[k] = irr[4 * tid + k]; vi[k] = iii[4 * tid + k]; }
        __syncthreads();                  // sg/Plo/Phi visible
        int t0 = tid << 4;
        {
            h2 x[16];
#pragma unroll
            for (int k = 0; k < 4; ++k) {
                x[4 * k]     = u2h(vr[k].x);
                x[4 * k + 1] = u2h(vr[k].y);
                x[4 * k + 2] = u2h(vr[k].z);
                x[4 * k + 3] = u2h(vr[k].w);
            }
#pragma unroll
            for (int p = 0; p < 4; ++p) {
                h2 c = sg[12 - p][0], s = sg[12 - p][1], ns = sg[12 - p][2];
                int m = 1 << p;
#pragma unroll
                for (int j = 0; j < 16; ++j)
                    if (!(j & m)) ry1h(x[j], x[j | m], c, s, ns);
            }
#pragma unroll
            for (int j = 0; j < 16; ++j) s_re[SWX(t0 + j)] = h2u(x[j]);
        }
        {
            h2 x[16];
#pragma unroll
            for (int k = 0; k < 4; ++k) {
                x[4 * k]     = u2h(vi[k].x);
                x[4 * k + 1] = u2h(vi[k].y);
                x[4 * k + 2] = u2h(vi[k].z);
                x[4 * k + 3] = u2h(vi[k].w);
            }
#pragma unroll
            for (int p = 0; p < 4; ++p) {
                h2 c = sg[12 - p][0], s = sg[12 - p][1], ns = sg[12 - p][2];
                int m = 1 << p;
#pragma unroll
                for (int j = 0; j < 16; ++j)
                    if (!(j & m)) ry1h(x[j], x[j | m], c, s, ns);
            }
#pragma unroll
            for (int j = 0; j < 16; ++j) s_im[SWX(t0 + j)] = h2u(x[j]);
        }
    }
    __syncthreads();

    // stage A: bits 4..7 (wires 13..10). Bank-safe map.
    {
        int w = tid >> 5;
        int bs = (tid & 15) | ((w & 1) << 8) | (((tid >> 4) & 1) << 9) | ((w >> 1) << 10);
        stage4h(s_re, sg, bs, 4, 8);
        stage4h(s_im, sg, bs, 4, 8);
    }
    __syncthreads();

    // stage B: bits 8..11 (wires 9..6). Group bits 0-7, 12.
    {
        int bs = (tid & 255) | ((tid >> 8) << 12);
        stage4h(s_re, sg, bs, 8, 4);
        stage4h(s_im, sg, bs, 8, 4);
    }
    __syncthreads();

    // wire 5 (bit 12) RY + diagonal RZ + CNOT-ladder permutation
    int pm = (__popc(H) & 1) ? (CHUNK - 1) : 0;
    int Hd = H ^ (H >> 1); Hd ^= Hd >> 2; Hd ^= Hd >> 4;   // invgray5
    h2 c5 = sg[0][0], s5 = sg[0][1], ns5 = sg[0][2];

    if (!LAST) {
        long obase = (long)b * DIM + ((long)Hd << CHUNK_BITS);
        __half2* dre = ore + obase;
        __half2* dim = oim + obase;
#pragma unroll
        for (int k = 0; k < 4; ++k) {
            int t = 2 * (tid + k * PL_THREADS);     // even, [0,4096)
            int uu = t + 4096;
            h2 rt = u2h(s_re[SWX(t)]),       it = u2h(s_im[SWX(t)]);
            h2 rt1 = u2h(s_re[SWX(t + 1)]),  it1 = u2h(s_im[SWX(t + 1)]);
            h2 ru = u2h(s_re[SWX(uu)]),      iu = u2h(s_im[SWX(uu)]);
            h2 ru1 = u2h(s_re[SWX(uu + 1)]), iu1 = u2h(s_im[SWX(uu + 1)]);
            ry1h(rt, ru, c5, s5, ns5);   ry1h(it, iu, c5, s5, ns5);
            ry1h(rt1, ru1, c5, s5, ns5); ry1h(it1, iu1, c5, s5, ns5);
            float2 lo0 = Plo[t & 63], lo1 = Plo[(t & 63) | 1];
            float2 hT = Phi[t >> 6], hU = Phi[(t >> 6) + 64];
            capply_h(rt, it, cmulf(lo0, hT));   capply_h(rt1, it1, cmulf(lo1, hT));
            capply_h(ru, iu, cmulf(lo0, hU));   capply_h(ru1, iu1, cmulf(lo1, hU));
            int q = invgray(t) ^ pm;
            int qu = q ^ 8191;                      // invgray(4096)=8191
            st_pair(dre, q, h2u(rt), h2u(rt1));  st_pair(dim, q, h2u(it), h2u(it1));
            st_pair(dre, qu, h2u(ru), h2u(ru1)); st_pair(dim, qu, h2u(iu), h2u(iu1));
        }
    } else {
        float a0[NUM_WIRES], a1[NUM_WIRES];
#pragma unroll
        for (int w = 0; w < NUM_WIRES; ++w) { a0[w] = 0.0f; a1[w] = 0.0f; }
        int hi = Hd << CHUNK_BITS;
#pragma unroll
        for (int k = 0; k < 4; ++k) {
            int t = 2 * (tid + k * PL_THREADS);
            int uu = t + 4096;
            h2 rt = u2h(s_re[SWX(t)]),       it = u2h(s_im[SWX(t)]);
            h2 rt1 = u2h(s_re[SWX(t + 1)]),  it1 = u2h(s_im[SWX(t + 1)]);
            h2 ru = u2h(s_re[SWX(uu)]),      iu = u2h(s_im[SWX(uu)]);
            h2 ru1 = u2h(s_re[SWX(uu + 1)]), iu1 = u2h(s_im[SWX(uu + 1)]);
            ry1h(rt, ru, c5, s5, ns5);   ry1h(it, iu, c5, s5, ns5);
            ry1h(rt1, ru1, c5, s5, ns5); ry1h(it1, iu1, c5, s5, ns5);
            int q = invgray(t) ^ pm;
            int qu = q ^ 8191;
            float2 frt = __half22float2(rt),   fit = __half22float2(it);
            float2 frt1 = __half22float2(rt1), fit1 = __half22float2(it1);
            float2 fru = __half22float2(ru),   fiu = __half22float2(iu);
            float2 fru1 = __half22float2(ru1), fiu1 = __half22float2(iu1);
            float2 pt  = make_float2(frt.x * frt.x + fit.x * fit.x,
                                     frt.y * frt.y + fit.y * fit.y);
            float2 pt1 = make_float2(frt1.x * frt1.x + fit1.x * fit1.x,
                                     frt1.y * frt1.y + fit1.y * fit1.y);
            float2 pu  = make_float2(fru.x * fru.x + fiu.x * fiu.x,
                                     fru.y * fru.y + fiu.y * fiu.y);
            float2 pu1 = make_float2(fru1.x * fru1.x + fiu1.x * fiu1.x,
                                     fru1.y * fru1.y + fiu1.y * fiu1.y);
            {
                int d = hi | q;
                unsigned bb0 = __float_as_uint(pt.x + pt1.x);
                unsigned bb1 = __float_as_uint(pt.y + pt1.y);
#pragma unroll
                for (int w = 0; w < 17; ++w) {
                    unsigned bit = (unsigned)(d >> (17 - w)) & 1u;
                    a0[w] += __uint_as_float(bb0 ^ (bit << 31));
                    a1[w] += __uint_as_float(bb1 ^ (bit << 31));
                }
                float d0 = pt.x - pt1.x, d1 = pt.y - pt1.y;
                a0[17] += (q & 1) ? -d0 : d0;
                a1[17] += (q & 1) ? -d1 : d1;
            }
            {
                int d = hi | qu;
                unsigned bb0 = __float_as_uint(pu.x + pu1.x);
                unsigned bb1 = __float_as_uint(pu.y + pu1.y);
#pragma unroll
                for (int w = 0; w < 17; ++w) {
                    unsigned bit = (unsigned)(d >> (17 - w)) & 1u;
                    a0[w] += __uint_as_float(bb0 ^ (bit << 31));
                    a1[w] += __uint_as_float(bb1 ^ (bit << 31));
                }
                float d0 = pu.x - pu1.x, d1 = pu.y - pu1.y;
                a0[17] += (qu & 1) ? -d0 : d0;
                a1[17] += (qu & 1) ? -d1 : d1;
            }
        }
#pragma unroll
        for (int w = 0; w < NUM_WIRES; ++w)
#pragma unroll
            for (int o = 16; o; o >>= 1) {
                a0[w] += __shfl_down_sync(0xFFFFFFFFu, a0[w], o);
                a1[w] += __shfl_down_sync(0xFFFFFFFFu, a1[w], o);
            }
        __syncthreads();
        float* scratch = (float*)smem_u;
        int warp = tid >> 5, lane = tid & 31;
        if (lane == 0) {
#pragma unroll
            for (int w = 0; w < NUM_WIRES; ++w) {
                scratch[(warp * 2 + 0) * NUM_WIRES + w] = a0[w];
                scratch[(warp * 2 + 1) * NUM_WIRES + w] = a1[w];
            }
        }
        __syncthreads();
        if (tid < 2 * NUM_WIRES) {
            int s = tid / NUM_WIRES, w = tid % NUM_WIRES;
            float sum = 0.0f;
#pragma unroll
            for (int k = 0; k < PL_THREADS / 32; ++k)
                sum += scratch[(k * 2 + s) * NUM_WIRES + w];
            partial[(((long)(2 * b + s)) * NCHUNK + H) * NUM_WIRES + w] = sum;
        }
    }
}

__global__ void k_head(const float* __restrict__ head_w,
                       const float* __restrict__ head_b,
                       float* __restrict__ out) {
    int b = threadIdx.x;
    if (b < BATCH) {
        float s = head_b[0];
#pragma unroll
        for (int w = 0; w < NUM_WIRES; ++w) {
            float f = 0.0f;
#pragma unroll
            for (int c = 0; c < NCHUNK; ++c)
                f += g_partial[((long)b * NCHUNK + c) * NUM_WIRES + w];
            s = fmaf(f, head_w[w], s);
        }
        out[b] = s;
    }
}

extern "C" void kernel_launch(void* const* d_in, const int* in_sizes, int n_in,
                              void* d_out, int out_size) {
    const float* state_re = (const float*)d_in[0];
    const float* state_im = (const float*)d_in[1];
    const float* params   = (const float*)d_in[2];
    const float* head_w   = (const float*)d_in[3];
    const float* head_b   = (const float*)d_in[4];
    float* out = (float*)d_out;

    const int shmem = 2 * CHUNK * (int)sizeof(unsigned);   // 64KB
    cudaFuncSetAttribute(k_pass_low<0>, cudaFuncAttributeMaxDynamicSharedMemorySize, shmem);
    cudaFuncSetAttribute(k_pass_low<1>, cudaFuncAttributeMaxDynamicSharedMemorySize, shmem);

    static __half2 *re0 = nullptr, *im0 = nullptr, *re1 = nullptr, *im1 = nullptr;
    static float* ptp = nullptr;
    if (!re0) {
        cudaGetSymbolAddress((void**)&re0, g_re0);
        cudaGetSymbolAddress((void**)&im0, g_im0);
        cudaGetSymbolAddress((void**)&re1, g_re1);
        cudaGetSymbolAddress((void**)&im1, g_im1);
        cudaGetSymbolAddress((void**)&ptp, g_partial);
    }

    const int ph_blocks = (GP * 2 * CHUNK) / PH_THREADS;   // 1024
    const int pl_blocks = GP * NCHUNK;                     // 512

    // L2-resident groups of GP=16 pairs (working set 67MB < L2)
    for (int grp = 0; grp < NPAIR / GP; ++grp) {
        long poff = (long)grp * GP * DIM;       // pair-plane offset
        long soff = (long)grp * GP * 2 * DIM;   // fp32 input offset
        __half2 *r0 = re0 + poff, *i0 = im0 + poff;
        __half2 *r1 = re1 + poff, *i1 = im1 + poff;
        float* part = ptp + (long)grp * GP * 2 * NCHUNK * NUM_WIRES;

        // layer 0
        k_first<<<ph_blocks, PH_THREADS>>>(state_re + soff, state_im + soff, r0, i0, params);
        k_pass_low<0><<<pl_blocks, PL_THREADS, shmem>>>(r0, i0, r1, i1, params, part, 0);
        // layer 1
        k_pass_high<<<ph_blocks, PH_THREADS>>>(r1, i1, params, 1);
        k_pass_low<0><<<pl_blocks, PL_THREADS, shmem>>>(r1, i1, r0, i0, params, part, 1);
        // layer 2
        k_pass_high<<<ph_blocks, PH_THREADS>>>(r0, i0, params, 2);
        k_pass_low<1><<<pl_blocks, PL_THREADS, shmem>>>(r0, i0, r1, i1, params, part, 2);
    }

    k_head<<<1, 64>>>(head_w, head_b, out);
}

// round 16
// speedup vs baseline: 1.4015x; 1.1266x over previous
#include <cuda_runtime.h>
#include <cuda_fp16.h>
#include <math.h>

#define NUM_WIRES 18
#define BATCH     64
#define NPAIR     32
#define DIM       262144           // 2^18
#define CHUNK_BITS 13
#define CHUNK     8192
#define NCHUNK    32
#define PL_THREADS 512
#define PH_THREADS 256

typedef unsigned long long u64;
typedef __half2 h2;

// SoA component planes; each half2 = (state_s0, state_s1)
__device__ __half2 g_re0[NPAIR * DIM];
__device__ __half2 g_im0[NPAIR * DIM];
__device__ __half2 g_re1[NPAIR * DIM];
__device__ __half2 g_im1[NPAIR * DIM];
__device__ float g_partial[BATCH * NCHUNK * NUM_WIRES];

// ---- packed f32x2 primitives (k_first only) ----
__device__ __forceinline__ u64 pk(float lo, float hi) {
    u64 r; asm("mov.b64 %0,{%1,%2};" : "=l"(r) : "f"(lo), "f"(hi)); return r;
}
__device__ __forceinline__ u64 pk2(float x) { return pk(x, x); }
__device__ __forceinline__ float2 up(u64 v) {
    float2 f; asm("mov.b64 {%0,%1},%2;" : "=f"(f.x), "=f"(f.y) : "l"(v)); return f;
}
__device__ __forceinline__ u64 fma2(u64 a, u64 b, u64 c) {
    u64 d; asm("fma.rn.f32x2 %0,%1,%2,%3;" : "=l"(d) : "l"(a), "l"(b), "l"(c)); return d;
}
__device__ __forceinline__ u64 mul2(u64 a, u64 b) {
    u64 d; asm("mul.rn.f32x2 %0,%1,%2;" : "=l"(d) : "l"(a), "l"(b)); return d;
}
__device__ __forceinline__ unsigned pk2hu(u64 v) {
    float2 f = up(v); __half2 h = __floats2half2_rn(f.x, f.y); return *(unsigned*)&h;
}
__device__ __forceinline__ void ry1(u64& a, u64& b, u64 c, u64 s, u64 ns) {
    u64 na = fma2(c, a, mul2(ns, b));
    b = fma2(s, a, mul2(c, b));
    a = na;
}

// ---- half2 primitives (main compute path) ----
__device__ __forceinline__ h2 u2h(unsigned u) { h2 h; *(unsigned*)&h = u; return h; }
__device__ __forceinline__ unsigned h2u(h2 h) { return *(unsigned*)&h; }
__device__ __forceinline__ void ry1h(h2& a, h2& b, h2 c, h2 s, h2 ns) {
    h2 na = __hfma2(c, a, __hmul2(ns, b));
    b = __hfma2(s, a, __hmul2(c, b));
    a = na;
}
__device__ __forceinline__ void capply_h(h2& r, h2& i, float2 p) {
    h2 pr = __float2half2_rn(p.x), pi = __float2half2_rn(p.y), npi = __float2half2_rn(-p.y);
    h2 nr = __hfma2(pr, r, __hmul2(npi, i));
    i = __hfma2(pr, i, __hmul2(pi, r));
    r = nr;
}
__device__ __forceinline__ float2 cmulf(float2 a, float2 b) {
    return make_float2(a.x * b.x - a.y * b.y, a.x * b.y + a.y * b.x);
}

// swizzle for 8B smem elements: bank-pair = (e ^ (e>>4)) & 15.
// Verified conflict-free (distinct bank pairs per half-warp) for fill,
// both stages, scatter and expval access patterns. Bijective on [0,8192).
__device__ __forceinline__ int SW8(int e) { return e ^ ((e >> 4) & 15); }
__device__ __forceinline__ int invgray(int t) {
    t ^= t >> 1; t ^= t >> 2; t ^= t >> 4; t ^= t >> 8; return t;
}
__device__ __forceinline__ void st_pair(__half2* pl, int q, unsigned va, unsigned vb) {
    uint2 o; o.x = (q & 1) ? vb : va; o.y = (q & 1) ? va : vb;
    *(uint2*)(pl + (q & ~1)) = o;
}

// ---------------------------------------------------------------------------
// pass_high: RY-only, wires 0..4 (bits 17..13), per component plane, in place.
// ---------------------------------------------------------------------------
__global__ void __launch_bounds__(PH_THREADS, 4)
k_pass_high(__half2* __restrict__ bre, __half2* __restrict__ bim,
            const float* __restrict__ params, int layer) {
    int gid = blockIdx.x * PH_THREADS + threadIdx.x;
    int u = gid & (CHUNK - 1);
    int r = gid >> CHUNK_BITS;
    __half2* pl = ((r & 1) ? bim : bre) + (long)(r >> 1) * DIM + u;

    h2 x[32];
#pragma unroll
    for (int j = 0; j < 32; ++j) x[j] = pl[(long)j << CHUNK_BITS];

#pragma unroll
    for (int w = 0; w < 5; ++w) {
        float ty = params[(layer * 2) * NUM_WIRES + w] * 0.5f;
        float sy, cy; sincosf(ty, &sy, &cy);
        h2 c = __float2half2_rn(cy), s = __float2half2_rn(sy), ns = __float2half2_rn(-sy);
        int m = 16 >> w;
#pragma unroll
        for (int j = 0; j < 32; ++j)
            if (!(j & m)) ry1h(x[j], x[j | m], c, s, ns);
    }
#pragma unroll
    for (int j = 0; j < 32; ++j) pl[(long)j << CHUNK_BITS] = x[j];
}

// layer-0 variant: fp32 inputs (rows 2p, 2p+1), fp32 math, writes half2 planes
__global__ void __launch_bounds__(PH_THREADS, 2)
k_first(const float* __restrict__ sre, const float* __restrict__ sim,
        __half2* __restrict__ ore, __half2* __restrict__ oim,
        const float* __restrict__ params) {
    int gid = blockIdx.x * PH_THREADS + threadIdx.x;
    int u = gid & (CHUNK - 1);
    int r = gid >> CHUNK_BITS;
    int c = r & 1, p = r >> 1;
    const float* src = c ? sim : sre;
    const float* r0 = src + (long)(2 * p) * DIM + u;
    const float* r1 = src + (long)(2 * p + 1) * DIM + u;

    u64 x[32];
#pragma unroll
    for (int j = 0; j < 32; ++j)
        x[j] = pk(r0[(long)j << CHUNK_BITS], r1[(long)j << CHUNK_BITS]);
#pragma unroll
    for (int w = 0; w < 5; ++w) {
        float ty = params[w] * 0.5f;
        float sy, cy; sincosf(ty, &sy, &cy);
        u64 cc = pk2(cy), s = pk2(sy), ns = pk2(-sy);
        int m = 16 >> w;
#pragma unroll
        for (int j = 0; j < 32; ++j)
            if (!(j & m)) ry1(x[j], x[j | m], cc, s, ns);
    }
    __half2* pl = (c ? oim : ore) + (long)p * DIM + u;
#pragma unroll
    for (int j = 0; j < 32; ++j)
        *(unsigned*)(pl + ((long)j << CHUNK_BITS)) = pk2hu(x[j]);
}

// 4-bit RY stage on interleaved (re,im) smem: 16 uint2 per group, offset sh.
__device__ __forceinline__ void stage4i(uint2* sp, const h2 (*sg)[3],
                                        int base, int sh, int wi0) {
    h2 xr[16], xi[16];
#pragma unroll
    for (int j = 0; j < 16; ++j) {
        uint2 v = sp[SW8(base | (j << sh))];
        xr[j] = u2h(v.x); xi[j] = u2h(v.y);
    }
#pragma unroll
    for (int p = 0; p < 4; ++p) {
        h2 c = sg[wi0 - p][0], s = sg[wi0 - p][1], ns = sg[wi0 - p][2];
        int m = 1 << p;
#pragma unroll
        for (int j = 0; j < 16; ++j)
            if (!(j & m)) {
                ry1h(xr[j], xr[j | m], c, s, ns);
                ry1h(xi[j], xi[j | m], c, s, ns);
            }
    }
#pragma unroll
    for (int j = 0; j < 16; ++j)
        sp[SW8(base | (j << sh))] = make_uint2(h2u(xr[j]), h2u(xi[j]));
}

// ---------------------------------------------------------------------------
// pass_low: wires 5..17 (bits 12..0); interleaved (re,im) uint2 smem (64KB,
// 2 CTAs/SM), half2 compute. Fill fuses bits 0..3 stage; two 4-bit smem
// stages; wire 5 + diagonal RZ phase fused with Gray scatter.
// LAST: expectation values (fp32), no RZ.
// ---------------------------------------------------------------------------
template <int LAST>
__global__ void __launch_bounds__(PL_THREADS, 2)
k_pass_low(const __half2* __restrict__ ire, const __half2* __restrict__ iim,
           __half2* __restrict__ ore, __half2* __restrict__ oim,
           const float* __restrict__ params, float* __restrict__ partial,
           int layer) {
    extern __shared__ uint2 sp[];        // 8192 x 8B = 64KB
    __shared__ h2 sg[13][3];             // RY coefs, wires 5..17 -> [w-5]
    __shared__ float2 Plo[64];           // phase for bits 0..5 (wires 17..12)
    __shared__ float2 Phi[128];          // phase for bits 6..12 + chunk phase
    int tid = threadIdx.x;

    int b = blockIdx.x >> 5;
    int H = blockIdx.x & 31;

    if (tid < 13) {
        float ty = params[(layer * 2) * NUM_WIRES + (5 + tid)] * 0.5f;
        float sy, cy; sincosf(ty, &sy, &cy);
        sg[tid][0] = __float2half2_rn(cy);
        sg[tid][1] = __float2half2_rn(sy);
        sg[tid][2] = __float2half2_rn(-sy);
    }
    if (!LAST && tid >= 32 && tid < 224) {
        int i = tid - 32;
        const float* tz = params + (layer * 2 + 1) * NUM_WIRES;
        if (i < 64) {
            float ang = 0.0f;
#pragma unroll
            for (int bb = 0; bb < 6; ++bb) {
                float h = tz[17 - bb] * 0.5f;
                ang += ((i >> bb) & 1) ? h : -h;
            }
            float sv, cv; sincosf(ang, &sv, &cv);
            Plo[i] = make_float2(cv, sv);
        } else {
            int hv = i - 64;
            float ang = 0.0f;
#pragma unroll
            for (int w = 0; w < 5; ++w) {           // chunk-const high-wire RZ
                float h = tz[w] * 0.5f;
                ang += ((H >> (4 - w)) & 1) ? h : -h;
            }
#pragma unroll
            for (int bb = 6; bb <= 12; ++bb) {
                float h = tz[17 - bb] * 0.5f;
                ang += ((hv >> (bb - 6)) & 1) ? h : -h;
            }
            float sv, cv; sincosf(ang, &sv, &cv);
            Phi[hv] = make_float2(cv, sv);
        }
    }

    long base = (long)b * DIM + ((long)H << CHUNK_BITS);

    // fill + fused bits 0..3 stage (wires 17..14), interleaved store
    {
        const uint4* irr = (const uint4*)(ire + base);
        const uint4* iii = (const uint4*)(iim + base);
        uint4 vr[4], vi[4];
#pragma unroll
        for (int k = 0; k < 4; ++k) { vr[k] = irr[4 * tid + k]; vi[k] = iii[4 * tid + k]; }
        __syncthreads();                  // sg/Plo/Phi visible
        int t0 = tid << 4;
        h2 xr[16], xi[16];
#pragma unroll
        for (int k = 0; k < 4; ++k) {
            xr[4 * k]     = u2h(vr[k].x);  xi[4 * k]     = u2h(vi[k].x);
            xr[4 * k + 1] = u2h(vr[k].y);  xi[4 * k + 1] = u2h(vi[k].y);
            xr[4 * k + 2] = u2h(vr[k].z);  xi[4 * k + 2] = u2h(vi[k].z);
            xr[4 * k + 3] = u2h(vr[k].w);  xi[4 * k + 3] = u2h(vi[k].w);
        }
#pragma unroll
        for (int p = 0; p < 4; ++p) {
            h2 c = sg[12 - p][0], s = sg[12 - p][1], ns = sg[12 - p][2];
            int m = 1 << p;
#pragma unroll
            for (int j = 0; j < 16; ++j)
                if (!(j & m)) {
                    ry1h(xr[j], xr[j | m], c, s, ns);
                    ry1h(xi[j], xi[j | m], c, s, ns);
                }
        }
#pragma unroll
        for (int j = 0; j < 16; ++j)
            sp[SW8(t0 + j)] = make_uint2(h2u(xr[j]), h2u(xi[j]));
    }
    __syncthreads();

    // stage A: bits 4..7 (wires 13..10). Bank-safe map.
    {
        int w = tid >> 5;
        int bs = (tid & 15) | ((w & 1) << 8) | (((tid >> 4) & 1) << 9) | ((w >> 1) << 10);
        stage4i(sp, sg, bs, 4, 8);
    }
    __syncthreads();

    // stage B: bits 8..11 (wires 9..6). Group bits 0-7, 12.
    {
        int bs = (tid & 255) | ((tid >> 8) << 12);
        stage4i(sp, sg, bs, 8, 4);
    }
    __syncthreads();

    // wire 5 (bit 12) RY + diagonal RZ + CNOT-ladder permutation
    int pm = (__popc(H) & 1) ? (CHUNK - 1) : 0;
    int Hd = H ^ (H >> 1); Hd ^= Hd >> 2; Hd ^= Hd >> 4;   // invgray5
    h2 c5 = sg[0][0], s5 = sg[0][1], ns5 = sg[0][2];

    if (!LAST) {
        long obase = (long)b * DIM + ((long)Hd << CHUNK_BITS);
        __half2* dre = ore + obase;
        __half2* dim = oim + obase;
#pragma unroll
        for (int k = 0; k < 4; ++k) {
            int t = 2 * (tid + k * PL_THREADS);     // even, [0,4096)
            int uu = t + 4096;
            uint2 vt = sp[SW8(t)], vt1 = sp[SW8(t + 1)];
            uint2 vu = sp[SW8(uu)], vu1 = sp[SW8(uu + 1)];
            h2 rt = u2h(vt.x), it = u2h(vt.y);
            h2 rt1 = u2h(vt1.x), it1 = u2h(vt1.y);
            h2 ru = u2h(vu.x), iu = u2h(vu.y);
            h2 ru1 = u2h(vu1.x), iu1 = u2h(vu1.y);
            ry1h(rt, ru, c5, s5, ns5);   ry1h(it, iu, c5, s5, ns5);
            ry1h(rt1, ru1, c5, s5, ns5); ry1h(it1, iu1, c5, s5, ns5);
            float2 lo0 = Plo[t & 63], lo1 = Plo[(t & 63) | 1];
            float2 hT = Phi[t >> 6], hU = Phi[(t >> 6) + 64];
            capply_h(rt, it, cmulf(lo0, hT));   capply_h(rt1, it1, cmulf(lo1, hT));
            capply_h(ru, iu, cmulf(lo0, hU));   capply_h(ru1, iu1, cmulf(lo1, hU));
            int q = invgray(t) ^ pm;
            int qu = q ^ 8191;                      // invgray(4096)=8191
            st_pair(dre, q, h2u(rt), h2u(rt1));  st_pair(dim, q, h2u(it), h2u(it1));
            st_pair(dre, qu, h2u(ru), h2u(ru1)); st_pair(dim, qu, h2u(iu), h2u(iu1));
        }
    } else {
        float a0[NUM_WIRES], a1[NUM_WIRES];
#pragma unroll
        for (int w = 0; w < NUM_WIRES; ++w) { a0[w] = 0.0f; a1[w] = 0.0f; }
        int hi = Hd << CHUNK_BITS;
#pragma unroll
        for (int k = 0; k < 4; ++k) {
            int t = 2 * (tid + k * PL_THREADS);
            int uu = t + 4096;
            uint2 vt = sp[SW8(t)], vt1 = sp[SW8(t + 1)];
            uint2 vu = sp[SW8(uu)], vu1 = sp[SW8(uu + 1)];
            h2 rt = u2h(vt.x), it = u2h(vt.y);
            h2 rt1 = u2h(vt1.x), it1 = u2h(vt1.y);
            h2 ru = u2h(vu.x), iu = u2h(vu.y);
            h2 ru1 = u2h(vu1.x), iu1 = u2h(vu1.y);
            ry1h(rt, ru, c5, s5, ns5);   ry1h(it, iu, c5, s5, ns5);
            ry1h(rt1, ru1, c5, s5, ns5); ry1h(it1, iu1, c5, s5, ns5);
            int q = invgray(t) ^ pm;
            int qu = q ^ 8191;
            float2 frt = __half22float2(rt),   fit = __half22float2(it);
            float2 frt1 = __half22float2(rt1), fit1 = __half22float2(it1);
            float2 fru = __half22float2(ru),   fiu = __half22float2(iu);
            float2 fru1 = __half22float2(ru1), fiu1 = __half22float2(iu1);
            float2 pt  = make_float2(frt.x * frt.x + fit.x * fit.x,
                                     frt.y * frt.y + fit.y * fit.y);
            float2 pt1 = make_float2(frt1.x * frt1.x + fit1.x * fit1.x,
                                     frt1.y * frt1.y + fit1.y * fit1.y);
            float2 pu  = make_float2(fru.x * fru.x + fiu.x * fiu.x,
                                     fru.y * fru.y + fiu.y * fiu.y);
            float2 pu1 = make_float2(fru1.x * fru1.x + fiu1.x * fiu1.x,
                                     fru1.y * fru1.y + fiu1.y * fiu1.y);
            {
                int d = hi | q;
                unsigned bb0 = __float_as_uint(pt.x + pt1.x);
                unsigned bb1 = __float_as_uint(pt.y + pt1.y);
#pragma unroll
                for (int w = 0; w < 17; ++w) {
                    unsigned bit = (unsigned)(d >> (17 - w)) & 1u;
                    a0[w] += __uint_as_float(bb0 ^ (bit << 31));
                    a1[w] += __uint_as_float(bb1 ^ (bit << 31));
                }
                float d0 = pt.x - pt1.x, d1 = pt.y - pt1.y;
                a0[17] += (q & 1) ? -d0 : d0;
                a1[17] += (q & 1) ? -d1 : d1;
            }
            {
                int d = hi | qu;
                unsigned bb0 = __float_as_uint(pu.x + pu1.x);
                unsigned bb1 = __float_as_uint(pu.y + pu1.y);
#pragma unroll
                for (int w = 0; w < 17; ++w) {
                    unsigned bit = (unsigned)(d >> (17 - w)) & 1u;
                    a0[w] += __uint_as_float(bb0 ^ (bit << 31));
                    a1[w] += __uint_as_float(bb1 ^ (bit << 31));
                }
                float d0 = pu.x - pu1.x, d1 = pu.y - pu1.y;
                a0[17] += (qu & 1) ? -d0 : d0;
                a1[17] += (qu & 1) ? -d1 : d1;
            }
        }
#pragma unroll
        for (int w = 0; w < NUM_WIRES; ++w)
#pragma unroll
            for (int o = 16; o; o >>= 1) {
                a0[w] += __shfl_down_sync(0xFFFFFFFFu, a0[w], o);
                a1[w] += __shfl_down_sync(0xFFFFFFFFu, a1[w], o);
            }
        __syncthreads();
        float* scratch = (float*)sp;
        int warp = tid >> 5, lane = tid & 31;
        if (lane == 0) {
#pragma unroll
            for (int w = 0; w < NUM_WIRES; ++w) {
                scratch[(warp * 2 + 0) * NUM_WIRES + w] = a0[w];
                scratch[(warp * 2 + 1) * NUM_WIRES + w] = a1[w];
            }
        }
        __syncthreads();
        if (tid < 2 * NUM_WIRES) {
            int s = tid / NUM_WIRES, w = tid % NUM_WIRES;
            float sum = 0.0f;
#pragma unroll
            for (int k = 0; k < PL_THREADS / 32; ++k)
                sum += scratch[(k * 2 + s) * NUM_WIRES + w];
            partial[(((long)(2 * b + s)) * NCHUNK + H) * NUM_WIRES + w] = sum;
        }
    }
}

__global__ void k_head(const float* __restrict__ head_w,
                       const float* __restrict__ head_b,
                       float* __restrict__ out) {
    int b = threadIdx.x;
    if (b < BATCH) {
        float s = head_b[0];
#pragma unroll
        for (int w = 0; w < NUM_WIRES; ++w) {
            float f = 0.0f;
#pragma unroll
            for (int c = 0; c < NCHUNK; ++c)
                f += g_partial[((long)b * NCHUNK + c) * NUM_WIRES + w];
            s = fmaf(f, head_w[w], s);
        }
        out[b] = s;
    }
}

extern "C" void kernel_launch(void* const* d_in, const int* in_sizes, int n_in,
                              void* d_out, int out_size) {
    const float* state_re = (const float*)d_in[0];
    const float* state_im = (const float*)d_in[1];
    const float* params   = (const float*)d_in[2];
    const float* head_w   = (const float*)d_in[3];
    const float* head_b   = (const float*)d_in[4];
    float* out = (float*)d_out;

    const int shmem = CHUNK * (int)sizeof(uint2);          // 64KB
    cudaFuncSetAttribute(k_pass_low<0>, cudaFuncAttributeMaxDynamicSharedMemorySize, shmem);
    cudaFuncSetAttribute(k_pass_low<1>, cudaFuncAttributeMaxDynamicSharedMemorySize, shmem);

    static __half2 *re0 = nullptr, *im0 = nullptr, *re1 = nullptr, *im1 = nullptr;
    static float* ptp = nullptr;
    if (!re0) {
        cudaGetSymbolAddress((void**)&re0, g_re0);
        cudaGetSymbolAddress((void**)&im0, g_im0);
        cudaGetSymbolAddress((void**)&re1, g_re1);
        cudaGetSymbolAddress((void**)&im1, g_im1);
        cudaGetSymbolAddress((void**)&ptp, g_partial);
    }

    const int ph_blocks = (NPAIR * 2 * CHUNK) / PH_THREADS;  // 2048
    const int pl_blocks = NPAIR * NCHUNK;                    // 1024

    // layer 0
    k_first<<<ph_blocks, PH_THREADS>>>(state_re, state_im, re0, im0, params);
    k_pass_low<0><<<pl_blocks, PL_THREADS, shmem>>>(re0, im0, re1, im1, params, ptp, 0);
    // layer 1
    k_pass_high<<<ph_blocks, PH_THREADS>>>(re1, im1, params, 1);
    k_pass_low<0><<<pl_blocks, PL_THREADS, shmem>>>(re1, im1, re0, im0, params, ptp, 1);
    // layer 2
    k_pass_high<<<ph_blocks, PH_THREADS>>>(re0, im0, params, 2);
    k_pass_low<1><<<pl_blocks, PL_THREADS, shmem>>>(re0, im0, re1, im1, params, ptp, 2);

    k_head<<<1, 64>>>(head_w, head_b, out);
}